// round 16
// baseline (speedup 1.0000x reference)
#include <cuda_runtime.h>
#include <cuda_fp16.h>
#include <cstdint>
#include <cstddef>

#define IN_F   4096
#define OUT_F  4096
#define MTOT   8192   // 4 * 2048

// ---------------- scratch (static device globals: allocation-free) -----------
__device__ __half g_Xh[(size_t)MTOT * IN_F];   // 64 MiB, tile-major swizzled
__device__ __half g_Wh[(size_t)OUT_F * IN_F];  // 32 MiB, tile-major swizzled
__device__ int g_cntX[64];
__device__ int g_cntW[16];
__device__ int g_tile;

// ---------------- PTX helpers ----------------
__device__ __forceinline__ uint32_t smem_u32(const void* p) {
    uint32_t r;
    asm("{ .reg .u64 t; cvta.to.shared.u64 t, %1; cvt.u32.u64 %0, t; }"
        : "=r"(r) : "l"(p));
    return r;
}
__device__ __forceinline__ void ldsm_x4(uint32_t* r, uint32_t addr) {
    asm volatile("ldmatrix.sync.aligned.m8n8.x4.shared.b16 {%0,%1,%2,%3}, [%4];"
                 : "=r"(r[0]), "=r"(r[1]), "=r"(r[2]), "=r"(r[3]) : "r"(addr));
}
__device__ __forceinline__ void mma16816(float* c, const uint32_t* a, const uint32_t* b) {
    asm volatile(
        "mma.sync.aligned.m16n8k16.row.col.f32.f16.f16.f32 "
        "{%0,%1,%2,%3}, {%4,%5,%6,%7}, {%8,%9}, {%0,%1,%2,%3};"
        : "+f"(c[0]), "+f"(c[1]), "+f"(c[2]), "+f"(c[3])
        : "r"(a[0]), "r"(a[1]), "r"(a[2]), "r"(a[3]), "r"(b[0]), "r"(b[1]));
}
__device__ __forceinline__ void bulk_g2s(uint32_t dst, const void* src, uint32_t bytes,
                                         uint32_t mbar) {
    asm volatile(
        "cp.async.bulk.shared::cta.global.mbarrier::complete_tx::bytes [%0], [%1], %2, [%3];"
        :: "r"(dst), "l"(src), "r"(bytes), "r"(mbar) : "memory");
}
__device__ __forceinline__ int ld_acq(const int* p) {
    int v;
    asm volatile("ld.acquire.gpu.s32 %0, [%1];" : "=r"(v) : "l"(p) : "memory");
    return v;
}
#define MBARRIER_INIT(addr, cnt) \
    asm volatile("mbarrier.init.shared.b64 [%0], %1;" :: "r"((uint32_t)(addr)), "r"((uint32_t)(cnt)) : "memory")
#define MBARRIER_EXPECT_TX(addr, bytes) \
    asm volatile("mbarrier.arrive.expect_tx.shared.b64 _, [%0], %1;" :: "r"((uint32_t)(addr)), "r"((uint32_t)(bytes)) : "memory")
#define MBARRIER_ARRIVE(addr) \
    asm volatile("mbarrier.arrive.release.cta.shared::cta.b64 _, [%0];" :: "r"((uint32_t)(addr)) : "memory")
#define MBARRIER_WAIT_PARITY(mbar_smem_addr, phase_parity) do {                         \
    uint32_t _mbar = (uint32_t)(mbar_smem_addr);                                        \
    uint32_t _parity = (uint32_t)(phase_parity);                                        \
    uint32_t _done;                                                                     \
    asm volatile("{\n\t.reg .pred p;\n\t"                                               \
        "mbarrier.try_wait.parity.acquire.cta.shared::cta.b64 p, [%1], %2;\n\t"         \
        "selp.b32 %0, 1, 0, p;\n\t}"                                                    \
        : "=r"(_done) : "r"(_mbar), "r"(_parity) : "memory");                           \
    if (!_done) {                                                                       \
        asm volatile("{\n\t.reg .pred P1;\n\t"                                          \
            "WAIT_LOOP_%=:\n\t"                                                         \
            "mbarrier.try_wait.parity.acquire.cta.shared::cta.b64 P1, [%0], %1, 0x989680;\n\t" \
            "@P1 bra.uni WAIT_DONE_%=;\n\t"                                             \
            "bra.uni WAIT_LOOP_%=;\n\t"                                                 \
            "WAIT_DONE_%=:\n\t}"                                                        \
            :: "r"(_mbar), "r"(_parity) : "memory");                                    \
    }                                                                                   \
} while (0)

// ---------------- config ----------------
#define TO 32
#define TI 512
#define N_FOLD_UNITS 1024
#define N_CONV_UNITS 2048
#define CONV_SPLIT 1024
#define NSTG 128
#define GRID_BLOCKS 296

#define BM 128
#define BN 128
#define BK 64
#define NST 3
#define A_SZ (BM * 128)                   // 16384
#define B_SZ (BN * 128)                   // 16384
#define ST_SZ (A_SZ + B_SZ)               // 32768
#define SMEM_T0 1024
#define FUSED_SMEM (SMEM_T0 + NST * ST_SZ) // 99328
#define KCH (IN_F / BK)                   // 64
#define NTILES ((MTOT / BM) * (OUT_F / BN))   // 2048
#define FULL_BAR(sb, s)  ((sb) + 8 * (s))
#define EMPTY_BAR(sb, s) ((sb) + 24 + 8 * (s))

// ---------------- init kernel: zero scheduler state -------------------------
__global__ void k_init() {
    int t = threadIdx.x;
    if (t < 64) g_cntX[t] = 0;
    if (t < 16) g_cntW[t] = 0;
    if (t == 0) g_tile = 0;
}

// ---------------- staging units ----------------------------------------------
__device__ void conv_unit(int v, int tid, const float4* __restrict__ x) {
    for (int i = tid; i < 4 * 512; i += 256) {
        int row = 4 * v + (i >> 9);
        int kg = i & 511;
        int g = row * 512 + kg;
        float4 v0 = x[g * 2], v1 = x[g * 2 + 1];
        __half2 h0 = __floats2half2_rn(v0.x, v0.y);
        __half2 h1 = __floats2half2_rn(v0.z, v0.w);
        __half2 h2 = __floats2half2_rn(v1.x, v1.y);
        __half2 h3 = __floats2half2_rn(v1.z, v1.w);
        uint4 o;
        o.x = *reinterpret_cast<uint32_t*>(&h0);
        o.y = *reinterpret_cast<uint32_t*>(&h1);
        o.z = *reinterpret_cast<uint32_t*>(&h2);
        o.w = *reinterpret_cast<uint32_t*>(&h3);
        int kchunk = kg >> 3, chunk = kg & 7;
        int r = row & 127, mtile = row >> 7;
        size_t off = ((size_t)(mtile * 64 + kchunk) << 14)
                   + (uint32_t)(r * 128 + (((chunk ^ (r & 7)) & 7) << 4));
        *reinterpret_cast<uint4*>(reinterpret_cast<char*>(g_Xh) + off) = o;
    }
}

__device__ void fold_unit(int u, int tid, char* smem,
                          const int* __restrict__ qw, const float* __restrict__ qs,
                          const float* __restrict__ A, const float* __restrict__ B) {
    float (*As)[TI + 4] = (float (*)[TI + 4])(smem + SMEM_T0);
    float (*Bs)[16]     = (float (*)[16])(smem + SMEM_T0 + 16 * (TI + 4) * 4);
    float* Ss           = (float*)(smem + SMEM_T0 + 16 * (TI + 4) * 4 + TO * 16 * 4);
    const int ob = u >> 3;
    const int cb = (u & 7) * TI;
    const int o0 = ob * TO;
    for (int t = tid; t < TO * 16; t += 256)
        Bs[t / 16][t % 16] = B[(size_t)(o0 + t / 16) * 16 + (t % 16)];
    if (tid < TO) Ss[tid] = qs[o0 + tid];
    for (int t = tid; t < 16 * (TI / 4); t += 256) {
        int r = t / (TI / 4), j = t % (TI / 4);
        float4 v = reinterpret_cast<const float4*>(A + (size_t)r * IN_F + cb)[j];
        *reinterpret_cast<float4*>(&As[r][j * 4]) = v;
    }
    __syncthreads();
    const int ro = tid >> 3;
    const int l8 = tid & 7;
    const int o = o0 + ro;
    const int ntile = o >> 8, rr = o & 255;
    const float s = Ss[ro];
    const float* brow = Bs[ro];
    #pragma unroll 4
    for (int j = 0; j < TI / 32; ++j) {
        int il = l8 * 4 + j * 32;
        int4 q4 = *reinterpret_cast<const int4*>(&qw[(size_t)o * IN_F + cb + il]);
        float a0 = q4.x * s, a1 = q4.y * s, a2 = q4.z * s, a3 = q4.w * s;
        #pragma unroll
        for (int r = 0; r < 16; ++r) {
            float b2 = 2.0f * brow[r];
            a0 = fmaf(b2, As[r][il + 0], a0);
            a1 = fmaf(b2, As[r][il + 1], a1);
            a2 = fmaf(b2, As[r][il + 2], a2);
            a3 = fmaf(b2, As[r][il + 3], a3);
        }
        __half2 h0 = __floats2half2_rn(a0, a1);
        __half2 h1 = __floats2half2_rn(a2, a3);
        uint2 w;
        w.x = *reinterpret_cast<uint32_t*>(&h0);
        w.y = *reinterpret_cast<uint32_t*>(&h1);
        int col = cb + il;
        int kchunk = col >> 6;
        int c6 = col & 63;
        int chunk = c6 >> 3, within = c6 & 7;
        size_t off = ((size_t)(ntile * 64 + kchunk) << 15)
                   + (uint32_t)(rr * 128 + (((chunk ^ (rr & 7)) & 7) << 4) + within * 2);
        *reinterpret_cast<uint2*>(reinterpret_cast<char*>(g_Wh) + off) = w;
    }
}

__device__ __forceinline__ const char* tileA(int t) {
    return reinterpret_cast<const char*>(g_Xh) + ((size_t)(t >> 5) * 64 << 14);
}
__device__ __forceinline__ const char* tileB(int t) {
    int ntile = t & 31;
    return reinterpret_cast<const char*>(g_Wh)
         + ((size_t)(ntile >> 1) * 64 << 15) + (size_t)(ntile & 1) * 16384;
}

// ---------------- fused persistent kernel ------------------------------------
__global__ void __launch_bounds__(256, 2)
k_fused(const float4* __restrict__ x,
        const int* __restrict__ qw, const float* __restrict__ qs,
        const float* __restrict__ A, const float* __restrict__ B,
        const float* __restrict__ bias, float* __restrict__ out) {
    extern __shared__ char smem[];
    uint32_t sb = smem_u32(smem);
    const int tid = threadIdx.x;
    const int bid = blockIdx.x;
    const int wid = tid >> 5, lid = tid & 31;
    const int wm = wid & 1;
    const int wn = wid >> 1;

    // -------- phase A: fold W on ALL blocks --------
    for (int u = bid; u < N_FOLD_UNITS; u += GRID_BLOCKS) {
        fold_unit(u, tid, smem, qw, qs, A, B);
        __threadfence();
        __syncthreads();
        if (tid == 0) atomicAdd(&g_cntW[u >> 6], 1);
        __syncthreads();
    }
    // -------- phase B1: conv mtiles 0..31 on ALL blocks --------
    for (int v = bid; v < CONV_SPLIT; v += GRID_BLOCKS) {
        conv_unit(v, tid, x);
        __threadfence();
        __syncthreads();
        if (tid == 0) atomicAdd(&g_cntX[v >> 5], 1);
        __syncthreads();
    }
    // -------- phase B2: conv mtiles 32..63 on blocks 0..NSTG-1 --------
    if (bid < NSTG) {
        for (int v = CONV_SPLIT + bid; v < N_CONV_UNITS; v += NSTG) {
            conv_unit(v, tid, x);
            __threadfence();
            __syncthreads();
            if (tid == 0) atomicAdd(&g_cntX[v >> 5], 1);
            __syncthreads();
        }
    }

    // -------- phase C: persistent GEMM, cross-tile pipelined --------
    volatile int* sm_t = (volatile int*)(smem + 64);
    if (tid == 0) {
        #pragma unroll
        for (int s = 0; s < NST; ++s) {
            MBARRIER_INIT(FULL_BAR(sb, s), 1);
            MBARRIER_INIT(EMPTY_BAR(sb, s), 8);
        }
        int t0 = atomicAdd(&g_tile, 1);
        *sm_t = t0;
    }
    __syncthreads();
    int t = *sm_t;
    const char *gA = nullptr, *gB = nullptr;     // producer copies (tid0)

    if (t < NTILES && tid == 0) {
        gA = tileA(t); gB = tileB(t);
        while (ld_acq(&g_cntW[(t & 31) >> 1]) < 64) __nanosleep(256);
        while (ld_acq(&g_cntX[t >> 5]) < 32)        __nanosleep(256);
        #pragma unroll
        for (int c = 0; c < NST; ++c) {
            uint32_t stg = sb + SMEM_T0 + c * ST_SZ;
            MBARRIER_EXPECT_TX(FULL_BAR(sb, c), ST_SZ);
            bulk_g2s(stg,        gA + ((size_t)c << 14), A_SZ, FULL_BAR(sb, c));
            bulk_g2s(stg + A_SZ, gB + ((size_t)c << 15), B_SZ, FULL_BAR(sb, c));
        }
    }

    int s = 0, q = 0;                 // persistent pipeline state across tiles
    while (t < NTILES) {
        float ac[4][4][4];
        #pragma unroll
        for (int i = 0; i < 4; ++i)
            #pragma unroll
            for (int j = 0; j < 4; ++j)
                #pragma unroll
                for (int k = 0; k < 4; ++k) ac[i][j][k] = 0.0f;

        int t2 = NTILES;              // next tile (tid0 only)
        const char *gA2 = nullptr, *gB2 = nullptr;

        for (int c = 0; c < KCH; ++c) {
            MBARRIER_WAIT_PARITY(FULL_BAR(sb, s), (uint32_t)(q & 1));

            uint32_t Ab = sb + SMEM_T0 + s * ST_SZ;
            uint32_t Bb = Ab + A_SZ;
            #pragma unroll
            for (int ks = 0; ks < BK / 16; ++ks) {
                uint32_t af[16], bf[8];
                #pragma unroll
                for (int i = 0; i < 4; ++i) {
                    int row = wm * 64 + i * 16 + (lid & 15);
                    int chunk = ks * 2 + (lid >> 4);
                    uint32_t addr = Ab + (uint32_t)(row * 128) + (((chunk ^ (row & 7)) & 7) << 4);
                    ldsm_x4(af + i * 4, addr);
                }
                #pragma unroll
                for (int j = 0; j < 2; ++j) {
                    int row = wn * 32 + j * 16 + ((lid >> 4) << 3) + (lid & 7);
                    int chunk = ks * 2 + ((lid >> 3) & 1);
                    uint32_t addr = Bb + (uint32_t)(row * 128) + (((chunk ^ (row & 7)) & 7) << 4);
                    ldsm_x4(bf + j * 4, addr);
                }
                #pragma unroll
                for (int i = 0; i < 4; ++i) {
                    #pragma unroll
                    for (int jj = 0; jj < 4; ++jj) {
                        mma16816(ac[i][jj], &af[i * 4], &bf[(jj >> 1) * 4 + (jj & 1) * 2]);
                    }
                }
            }

            if (lid == 0) MBARRIER_ARRIVE(EMPTY_BAR(sb, s));

            if (tid == 0) {
                int pc = c + NST;
                if (pc < KCH) {
                    MBARRIER_WAIT_PARITY(EMPTY_BAR(sb, s), (uint32_t)(q & 1));
                    uint32_t stg = sb + SMEM_T0 + s * ST_SZ;
                    MBARRIER_EXPECT_TX(FULL_BAR(sb, s), ST_SZ);
                    bulk_g2s(stg,        gA + ((size_t)pc << 14), A_SZ, FULL_BAR(sb, s));
                    bulk_g2s(stg + A_SZ, gB + ((size_t)pc << 15), B_SZ, FULL_BAR(sb, s));
                } else {
                    if (pc == KCH) {   // first overflow: grab + prepare next tile
                        t2 = atomicAdd(&g_tile, 1);
                        *sm_t = t2;
                        if (t2 < NTILES) {
                            gA2 = tileA(t2); gB2 = tileB(t2);
                            while (ld_acq(&g_cntW[(t2 & 31) >> 1]) < 64) __nanosleep(256);
                            while (ld_acq(&g_cntX[t2 >> 5]) < 32)        __nanosleep(256);
                        }
                    }
                    if (t2 < NTILES) {
                        int nc = pc - KCH;            // next tile chunk 0..NST-1
                        MBARRIER_WAIT_PARITY(EMPTY_BAR(sb, s), (uint32_t)(q & 1));
                        uint32_t stg = sb + SMEM_T0 + s * ST_SZ;
                        MBARRIER_EXPECT_TX(FULL_BAR(sb, s), ST_SZ);
                        bulk_g2s(stg,        gA2 + ((size_t)nc << 14), A_SZ, FULL_BAR(sb, s));
                        bulk_g2s(stg + A_SZ, gB2 + ((size_t)nc << 15), B_SZ, FULL_BAR(sb, s));
                    }
                }
            }
            ++s; if (s == NST) { s = 0; ++q; }
        }

        // epilogue for tile t (overlaps next tile's in-flight loads)
        const int m0 = (t >> 5) * BM, n0 = (t & 31) * BN;
        const int mbase = m0 + wm * 64 + (lid >> 2);
        const int nbase = n0 + wn * 32 + (lid & 3) * 2;
        #pragma unroll
        for (int jj = 0; jj < 4; ++jj) {
            int n = nbase + jj * 8;
            float b0 = bias[n], b1 = bias[n + 1];
            #pragma unroll
            for (int i = 0; i < 4; ++i) {
                int m = mbase + i * 16;
                float2 v0 = make_float2(ac[i][jj][0] + b0, ac[i][jj][1] + b1);
                float2 v1 = make_float2(ac[i][jj][2] + b0, ac[i][jj][3] + b1);
                *reinterpret_cast<float2*>(&out[(size_t)m * OUT_F + n]) = v0;
                *reinterpret_cast<float2*>(&out[(size_t)(m + 8) * OUT_F + n]) = v1;
            }
        }

        __syncthreads();              // order: tid0 wrote sm_t during chunk KCH-NST
        t = *sm_t;
        if (tid == 0) { gA = gA2; gB = gB2; }
    }
}

// ---------------- launcher ----------------
extern "C" void kernel_launch(void* const* d_in, const int* in_sizes, int n_in,
                              void* d_out, int out_size) {
    const float* x    = (const float*)d_in[0];
    const int*   qw   = (const int*)  d_in[1];
    const float* qs   = (const float*)d_in[2];
    const float* bias = (const float*)d_in[3];
    const float* lA   = (const float*)d_in[4];
    const float* lB   = (const float*)d_in[5];
    float* out = (float*)d_out;

    cudaFuncSetAttribute(k_fused, cudaFuncAttributeMaxDynamicSharedMemorySize, FUSED_SMEM);

    k_init<<<1, 128>>>();
    k_fused<<<GRID_BLOCKS, 256, FUSED_SMEM>>>(reinterpret_cast<const float4*>(x),
                                              qw, qs, lA, lB, bias, out);
}

// round 17
// speedup vs baseline: 1.0327x; 1.0327x over previous
#include <cuda_runtime.h>
#include <cuda_fp16.h>
#include <cstdint>
#include <cstddef>

#define IN_F   4096
#define OUT_F  4096
#define MTOT   8192   // 4 * 2048

// ---------------- scratch (static device globals: allocation-free) -----------
// Tile-major, pre-swizzled layouts (exactly what the GEMM wants in smem):
// g_Xh: [mtile128(64)][kchunk(64)] blocks of 16384B = 128 rows x 128B (swizzled)
// g_Wh: [ntile256(16)][kchunk(64)] blocks of 32768B = 256 rows x 128B (swizzled)
__device__ __half g_Xh[(size_t)MTOT * IN_F];   // 64 MiB
__device__ __half g_Wh[(size_t)OUT_F * IN_F];  // 32 MiB

// ---------------- PTX helpers ----------------
__device__ __forceinline__ uint32_t smem_u32(const void* p) {
    uint32_t r;
    asm("{ .reg .u64 t; cvta.to.shared.u64 t, %1; cvt.u32.u64 %0, t; }"
        : "=r"(r) : "l"(p));
    return r;
}
__device__ __forceinline__ void ldsm_x4(uint32_t* r, uint32_t addr) {
    asm volatile("ldmatrix.sync.aligned.m8n8.x4.shared.b16 {%0,%1,%2,%3}, [%4];"
                 : "=r"(r[0]), "=r"(r[1]), "=r"(r[2]), "=r"(r[3]) : "r"(addr));
}
__device__ __forceinline__ void mma16816(float* c, const uint32_t* a, const uint32_t* b) {
    asm volatile(
        "mma.sync.aligned.m16n8k16.row.col.f32.f16.f16.f32 "
        "{%0,%1,%2,%3}, {%4,%5,%6,%7}, {%8,%9}, {%0,%1,%2,%3};"
        : "+f"(c[0]), "+f"(c[1]), "+f"(c[2]), "+f"(c[3])
        : "r"(a[0]), "r"(a[1]), "r"(a[2]), "r"(a[3]), "r"(b[0]), "r"(b[1]));
}
__device__ __forceinline__ void bulk_g2s(uint32_t dst, const void* src, uint32_t bytes,
                                         uint32_t mbar) {
    asm volatile(
        "cp.async.bulk.shared::cta.global.mbarrier::complete_tx::bytes [%0], [%1], %2, [%3];"
        :: "r"(dst), "l"(src), "r"(bytes), "r"(mbar) : "memory");
}
#define MBARRIER_INIT(addr, cnt) \
    asm volatile("mbarrier.init.shared.b64 [%0], %1;" :: "r"((uint32_t)(addr)), "r"((uint32_t)(cnt)) : "memory")
#define MBARRIER_EXPECT_TX(addr, bytes) \
    asm volatile("mbarrier.arrive.expect_tx.shared.b64 _, [%0], %1;" :: "r"((uint32_t)(addr)), "r"((uint32_t)(bytes)) : "memory")
#define MBARRIER_ARRIVE(addr) \
    asm volatile("mbarrier.arrive.release.cta.shared::cta.b64 _, [%0];" :: "r"((uint32_t)(addr)) : "memory")
#define MBARRIER_WAIT_PARITY(mbar_smem_addr, phase_parity) do {                         \
    uint32_t _mbar = (uint32_t)(mbar_smem_addr);                                        \
    uint32_t _parity = (uint32_t)(phase_parity);                                        \
    uint32_t _done;                                                                     \
    asm volatile("{\n\t.reg .pred p;\n\t"                                               \
        "mbarrier.try_wait.parity.acquire.cta.shared::cta.b64 p, [%1], %2;\n\t"         \
        "selp.b32 %0, 1, 0, p;\n\t}"                                                    \
        : "=r"(_done) : "r"(_mbar), "r"(_parity) : "memory");                           \
    if (!_done) {                                                                       \
        asm volatile("{\n\t.reg .pred P1;\n\t"                                          \
            "WAIT_LOOP_%=:\n\t"                                                         \
            "mbarrier.try_wait.parity.acquire.cta.shared::cta.b64 P1, [%0], %1, 0x989680;\n\t" \
            "@P1 bra.uni WAIT_DONE_%=;\n\t"                                             \
            "bra.uni WAIT_LOOP_%=;\n\t"                                                 \
            "WAIT_DONE_%=:\n\t}"                                                        \
            :: "r"(_mbar), "r"(_parity) : "memory");                                    \
    }                                                                                   \
} while (0)

// ---------------- fused staging kernel (R11/R12 form, 2D fold split) --------
#define TO 32
#define TI 512
#define FOLD_RS   (OUT_F / TO)       // 128 row strips
#define FOLD_CS   (IN_F / TI)        // 8 col strips
#define FOLD_TOTAL (FOLD_RS * FOLD_CS)   // 1024
#define CONV_BLOCKS 4096
#define STAGE_GRID (FOLD_TOTAL + CONV_BLOCKS)

__global__ void k_stage(const float4* __restrict__ x,
                        const int* __restrict__ qw, const float* __restrict__ qs,
                        const float* __restrict__ A, const float* __restrict__ B) {
    const int tid = threadIdx.x;                  // 256
    if (blockIdx.x >= FOLD_TOTAL) {
        // ---- convert x ----
        const int ngroups = MTOT * IN_F / 8;      // 16B groups
        int bid = blockIdx.x - FOLD_TOTAL;
        int stride = CONV_BLOCKS * 256;
        for (int g = bid * 256 + tid; g < ngroups; g += stride) {
            float4 v0 = x[g * 2], v1 = x[g * 2 + 1];
            __half2 h0 = __floats2half2_rn(v0.x, v0.y);
            __half2 h1 = __floats2half2_rn(v0.z, v0.w);
            __half2 h2 = __floats2half2_rn(v1.x, v1.y);
            __half2 h3 = __floats2half2_rn(v1.z, v1.w);
            uint4 o;
            o.x = *reinterpret_cast<uint32_t*>(&h0);
            o.y = *reinterpret_cast<uint32_t*>(&h1);
            o.z = *reinterpret_cast<uint32_t*>(&h2);
            o.w = *reinterpret_cast<uint32_t*>(&h3);
            int m = g >> 9;                 // 512 groups per row
            int kg = g & 511;
            int kchunk = kg >> 3, chunk = kg & 7;
            int r = m & 127, mtile = m >> 7;
            size_t off = ((size_t)(mtile * 64 + kchunk) << 14)
                       + (uint32_t)(r * 128 + (((chunk ^ (r & 7)) & 7) << 4));
            *reinterpret_cast<uint4*>(reinterpret_cast<char*>(g_Xh) + off) = o;
        }
        return;
    }
    // ---- fold W: one (32-row x 512-col) tile per block ----
    __shared__ float As[16][TI + 4];
    __shared__ float Bs[TO][16];
    __shared__ float Ss[TO];
    const int ob = blockIdx.x >> 3;              // row strip 0..127
    const int cb = (blockIdx.x & 7) * TI;        // col strip base
    const int o0 = ob * TO;
    for (int t = tid; t < TO * 16; t += 256)
        Bs[t / 16][t % 16] = B[(size_t)(o0 + t / 16) * 16 + (t % 16)];
    if (tid < TO) Ss[tid] = qs[o0 + tid];
    for (int t = tid; t < 16 * (TI / 4); t += 256) {
        int r = t / (TI / 4), j = t % (TI / 4);
        float4 v = reinterpret_cast<const float4*>(A + (size_t)r * IN_F + cb)[j];
        *reinterpret_cast<float4*>(&As[r][j * 4]) = v;
    }
    __syncthreads();
    const int ro = tid >> 3;    // row 0..31
    const int l8 = tid & 7;     // 0..7
    const int o = o0 + ro;
    const int ntile = o >> 8, rr = o & 255;
    const float s = Ss[ro];
    const float* brow = Bs[ro];
    #pragma unroll 4
    for (int j = 0; j < TI / 32; ++j) {
        int il = l8 * 4 + j * 32;
        int4 q4 = *reinterpret_cast<const int4*>(&qw[(size_t)o * IN_F + cb + il]);
        float a0 = q4.x * s, a1 = q4.y * s, a2 = q4.z * s, a3 = q4.w * s;
        #pragma unroll
        for (int r = 0; r < 16; ++r) {
            float b2 = 2.0f * brow[r];
            a0 = fmaf(b2, As[r][il + 0], a0);
            a1 = fmaf(b2, As[r][il + 1], a1);
            a2 = fmaf(b2, As[r][il + 2], a2);
            a3 = fmaf(b2, As[r][il + 3], a3);
        }
        __half2 h0 = __floats2half2_rn(a0, a1);
        __half2 h1 = __floats2half2_rn(a2, a3);
        uint2 w;
        w.x = *reinterpret_cast<uint32_t*>(&h0);
        w.y = *reinterpret_cast<uint32_t*>(&h1);
        int col = cb + il;
        int kchunk = col >> 6;
        int c6 = col & 63;
        int chunk = c6 >> 3, within = c6 & 7;   // within in {0,4}
        size_t off = ((size_t)(ntile * 64 + kchunk) << 15)
                   + (uint32_t)(rr * 128 + (((chunk ^ (rr & 7)) & 7) << 4) + within * 2);
        *reinterpret_cast<uint2*>(reinterpret_cast<char*>(g_Wh) + off) = w;
    }
}

// ---------------- GEMM: bulk-DMA pipeline, BM=128 x BN=128, 2 CTAs/SM -------
// 256 threads = 8 warps as 2(m) x 4(n); warp tile 64x32; 3 stages (97 KB/CTA).
// Full/empty mbarrier producer-consumer; producer = warp 7 lane 0 (highest-
// priority warp under hi-wid-first arbiter: finishes MMAs first, sleeps on the
// empty barrier, issues the refill immediately on the last consumer's arrival).
#define BM 128
#define BN 128
#define BK 64
#define NST 3
#define A_SZ (BM * 128)                   // 16384
#define B_SZ (BN * 128)                   // 16384
#define ST_SZ (A_SZ + B_SZ)               // 32768
#define SMEM_T0 1024
#define GEMM_SMEM (SMEM_T0 + NST * ST_SZ) // 99328
#define GEMM_THREADS 256
#define KCH (IN_F / BK)                   // 64
#define PRODUCER_TID 224                  // warp 7, lane 0
#define FULL_BAR(sb, s)  ((sb) + 8 * (s))          // [0, 24)
#define EMPTY_BAR(sb, s) ((sb) + 24 + 8 * (s))     // [24, 48)

__global__ void __launch_bounds__(GEMM_THREADS, 2)
k_gemm(const float* __restrict__ bias, float* __restrict__ out) {
    extern __shared__ char smem[];
    uint32_t sb = smem_u32(smem);
    const int tid = threadIdx.x;
    const int wid = tid >> 5, lid = tid & 31;
    const int wm = wid & 1;          // 0..1  (m: 64-row halves)
    const int wn = wid >> 1;         // 0..3  (n: 32-col slices)
    const int mtile = blockIdx.y;    // 0..63 (128-row)
    const int ntile = blockIdx.x;    // 0..31 (128-col)
    const char* gA = reinterpret_cast<const char*>(g_Xh) + ((size_t)mtile * 64 << 14);
    const char* gB = reinterpret_cast<const char*>(g_Wh)
                   + ((size_t)(ntile >> 1) * 64 << 15) + (size_t)(ntile & 1) * 16384;

    float ac[4][4][4];
    #pragma unroll
    for (int i = 0; i < 4; ++i)
        #pragma unroll
        for (int j = 0; j < 4; ++j)
            #pragma unroll
            for (int k = 0; k < 4; ++k) ac[i][j][k] = 0.0f;

    if (tid == 0) {
        #pragma unroll
        for (int s = 0; s < NST; ++s) {
            MBARRIER_INIT(FULL_BAR(sb, s), 1);
            MBARRIER_INIT(EMPTY_BAR(sb, s), 8);   // one arrive per warp
        }
    }
    __syncthreads();

    if (tid == 0) {
        #pragma unroll
        for (int c = 0; c < NST; ++c) {
            uint32_t stg = sb + SMEM_T0 + c * ST_SZ;
            MBARRIER_EXPECT_TX(FULL_BAR(sb, c), ST_SZ);
            bulk_g2s(stg,        gA + ((size_t)c << 14), A_SZ, FULL_BAR(sb, c));
            bulk_g2s(stg + A_SZ, gB + ((size_t)c << 15), B_SZ, FULL_BAR(sb, c));
        }
    }

    int s = 0, q = 0;    // stage = c % NST, q = c / NST; parity = q & 1
    for (int c = 0; c < KCH; ++c) {
        MBARRIER_WAIT_PARITY(FULL_BAR(sb, s), (uint32_t)(q & 1));

        uint32_t Ab = sb + SMEM_T0 + s * ST_SZ;
        uint32_t Bb = Ab + A_SZ;
        #pragma unroll
        for (int ks = 0; ks < BK / 16; ++ks) {       // 4
            uint32_t af[16], bf[8];
            #pragma unroll
            for (int i = 0; i < 4; ++i) {
                int row = wm * 64 + i * 16 + (lid & 15);
                int chunk = ks * 2 + (lid >> 4);
                uint32_t addr = Ab + (uint32_t)(row * 128) + (((chunk ^ (row & 7)) & 7) << 4);
                ldsm_x4(af + i * 4, addr);
            }
            #pragma unroll
            for (int j = 0; j < 2; ++j) {
                int row = wn * 32 + j * 16 + ((lid >> 4) << 3) + (lid & 7);
                int chunk = ks * 2 + ((lid >> 3) & 1);
                uint32_t addr = Bb + (uint32_t)(row * 128) + (((chunk ^ (row & 7)) & 7) << 4);
                ldsm_x4(bf + j * 4, addr);
            }
            #pragma unroll
            for (int i = 0; i < 4; ++i) {
                #pragma unroll
                for (int jj = 0; jj < 4; ++jj) {
                    mma16816(ac[i][jj], &af[i * 4], &bf[(jj >> 1) * 4 + (jj & 1) * 2]);
                }
            }
        }

        // this warp is done reading stage s for consumption q
        if (lid == 0) MBARRIER_ARRIVE(EMPTY_BAR(sb, s));

        // producer (warp 7 lane 0): refill stage s with chunk c+NST once all
        // 8 warps have arrived. Warp 7 finishes its MMAs first (hi-wid-first
        // arbiter) so this wait sleeps and wakes on the LAST consumer arrival.
        if (tid == PRODUCER_TID && c + NST < KCH) {
            MBARRIER_WAIT_PARITY(EMPTY_BAR(sb, s), (uint32_t)(q & 1));
            int nc = c + NST;
            uint32_t stg = sb + SMEM_T0 + s * ST_SZ;
            MBARRIER_EXPECT_TX(FULL_BAR(sb, s), ST_SZ);
            bulk_g2s(stg,        gA + ((size_t)nc << 14), A_SZ, FULL_BAR(sb, s));
            bulk_g2s(stg + A_SZ, gB + ((size_t)nc << 15), B_SZ, FULL_BAR(sb, s));
        }
        ++s; if (s == NST) { s = 0; ++q; }
    }

    // epilogue: write 64x32 warp tile with bias (per-warp, no sync needed)
    const int m0 = mtile * BM, n0 = ntile * BN;
    const int mbase = m0 + wm * 64 + (lid >> 2);
    const int nbase = n0 + wn * 32 + (lid & 3) * 2;
    #pragma unroll
    for (int jj = 0; jj < 4; ++jj) {
        int n = nbase + jj * 8;
        float b0 = bias[n], b1 = bias[n + 1];
        #pragma unroll
        for (int i = 0; i < 4; ++i) {
            int m = mbase + i * 16;
            float2 v0 = make_float2(ac[i][jj][0] + b0, ac[i][jj][1] + b1);
            float2 v1 = make_float2(ac[i][jj][2] + b0, ac[i][jj][3] + b1);
            *reinterpret_cast<float2*>(&out[(size_t)m * OUT_F + n]) = v0;
            *reinterpret_cast<float2*>(&out[(size_t)(m + 8) * OUT_F + n]) = v1;
        }
    }
}

// ---------------- launcher ----------------
extern "C" void kernel_launch(void* const* d_in, const int* in_sizes, int n_in,
                              void* d_out, int out_size) {
    const float* x    = (const float*)d_in[0];
    const int*   qw   = (const int*)  d_in[1];
    const float* qs   = (const float*)d_in[2];
    const float* bias = (const float*)d_in[3];
    const float* lA   = (const float*)d_in[4];
    const float* lB   = (const float*)d_in[5];
    float* out = (float*)d_out;

    cudaFuncSetAttribute(k_gemm, cudaFuncAttributeMaxDynamicSharedMemorySize, GEMM_SMEM);

    k_stage<<<STAGE_GRID, 256>>>(reinterpret_cast<const float4*>(x), qw, qs, lA, lB);
    k_gemm<<<dim3(OUT_F / BN, MTOT / BM), GEMM_THREADS, GEMM_SMEM>>>(bias, out);
}